// round 7
// baseline (speedup 1.0000x reference)
#include <cuda_runtime.h>

typedef unsigned long long u64;

#define NT 1024
#define BT 64
#define B_TOT 8192
#define T_STEPS 30
#define WARM 24

__device__ __forceinline__ u64 pack2(float lo, float hi){
    u64 r; asm("mov.b64 %0, {%1, %2};" : "=l"(r) : "f"(lo), "f"(hi)); return r;
}
__device__ __forceinline__ void unpack2(u64 v, float& lo, float& hi){
    asm("mov.b64 {%0, %1}, %2;" : "=f"(lo), "=f"(hi) : "l"(v));
}
__device__ __forceinline__ u64 fma2(u64 a, u64 b, u64 c){
    u64 d; asm("fma.rn.f32x2 %0, %1, %2, %3;" : "=l"(d) : "l"(a), "l"(b), "l"(c)); return d;
}
__device__ __forceinline__ float sig_(float x){ return __fdividef(1.f, 1.f + __expf(-x)); }
__device__ __forceinline__ float tanh_(float x){ return 1.f - 2.f * __fdividef(1.f, __expf(2.f * x) + 1.f); }

#define CPA16(dst_u32, src) asm volatile("cp.async.cg.shared.global [%0], [%1], 16;" :: "r"(dst_u32), "l"(src))
#define CPA_COMMIT() asm volatile("cp.async.commit_group;")
#define CPA_WAIT()   asm volatile("cp.async.wait_group 0;")

// floats: wsm 2*4096 | hsm 136*64 | csm 128*64 | m1sm 128*64 | cbz 512 | cb1,cb2,cwo 384 | red 64*17 | predb 64
#define SMEM_FLOATS (8192 + 136*64 + 128*64 + 128*64 + 512 + 384 + 64*17 + 64)
#define SMEM_BYTES (SMEM_FLOATS * 4)

__global__ void __launch_bounds__(NT, 1)
fused_lstm_kernel(const float* __restrict__ x0, const float* __restrict__ x1,
                  const float* __restrict__ x2, const float* __restrict__ x3,
                  const float* __restrict__ x4, const float* __restrict__ x5,
                  const float* __restrict__ x6, const float* __restrict__ irr,
                  const float* __restrict__ Wi, const float* __restrict__ Wh,
                  const float* __restrict__ bz, const float* __restrict__ W1,
                  const float* __restrict__ b1, const float* __restrict__ W2,
                  const float* __restrict__ b2, const float* __restrict__ Wout,
                  const float* __restrict__ bout, float* __restrict__ out)
{
    extern __shared__ float smem[];
    float* wsm   = smem;                 // 2 x 4096 weight staging (16B aligned)
    float* hsm   = wsm  + 8192;          // [136][64]: 0-127 h, 128-135 features
    float* csm   = hsm  + 136 * 64;      // [128][64] c-state
    float* m1sm  = csm  + 128 * 64;      // [128][64]
    float* cbz   = m1sm + 128 * 64;      // 512
    float* cb1   = cbz  + 512;           // 128
    float* cb2   = cb1  + 128;           // 128
    float* cwo   = cb2  + 128;           // 128
    float* red   = cwo  + 128;           // [64][17]
    float* predb = red  + 64 * 17;       // 64

    const int tid = threadIdx.x;
    const int l   = tid & 31;            // lane -> rows l and l+32
    const int w   = tid >> 5;            // warp 0..31 -> channel slice
    const int ch0 = w << 2;              // z: 4 channels per warp
    const int r1  = l, r2 = l + 32;
    const int b0  = blockIdx.x * BT;

    // init h, c = 0; stage biases/wout
    for (int i = tid; i < 128 * 64; i += NT){ csm[i] = 0.f; hsm[i] = 0.f; }
    for (int i = tid; i < 512; i += NT) cbz[i] = bz[i];
    if (tid < 128){ cb1[tid] = b1[tid]; cb2[tid] = b2[tid]; cwo[tid] = Wout[tid]; }
    const float boutv = bout[0];

    // feature pointers: tid<512 handles (feat lf, row lr)
    const int lf = tid >> 6, lr = tid & 63;
    const float* fptr = x0; int tmax = 0;
    if (tid < 512){
        const float* p;
        if      (lf == 0) p = x0; else if (lf == 1) p = x1;
        else if (lf == 2) p = x2; else if (lf == 3) p = x3;
        else if (lf == 4) p = x4; else if (lf == 5) p = x5;
        else if (lf == 6) p = x6; else              p = irr;
        int gb = b0 + lr;
        fptr = (lf < 7) ? (p + gb * T_STEPS) : (p + gb * WARM);
        tmax = (lf < 7) ? (T_STEPS - 1) : (WARM - 1);
    }

    // prologue: stage Wh chunk 0 (4096 floats, 1 CPA16/thread)
    {
        unsigned d = (unsigned)__cvta_generic_to_shared(wsm);
        CPA16(d + tid * 16, Wh + tid * 4);
        CPA_COMMIT(); CPA_WAIT();
    }
    int pb = 0;
    __syncthreads();

    for (int t = 0; t < T_STEPS; ++t){
        // ---- stage step inputs into hsm rows 128..135 ----
        if (tid < 512){
            int ti = t < tmax ? t : tmax;
            float gv = __ldg(fptr + ti);
            hsm[(128 + lf) * 64 + lr] = (lf < 7 || t < WARM) ? gv : predb[lr];
        }

        // ================ z = [h, feat] @ [Wh; Wi] + b ================
        // acc[r][q][p]: row (r1/r2), gate q, channel pair (ch0+2p, ch0+2p+1)
        u64 acc[2][4][2];
        #pragma unroll
        for (int q = 0; q < 4; q++){
            ulonglong2 bq = *reinterpret_cast<const ulonglong2*>(cbz + (q << 7) + ch0);
            acc[0][q][0] = bq.x; acc[0][q][1] = bq.y;
            acc[1][q][0] = bq.x; acc[1][q][1] = bq.y;
        }
        for (int c = 0; c <= 16; ++c){
            const float* nsrc = (c < 15) ? (Wh + (c + 1) * 4096) : ((c == 15) ? Wi : W1);
            {
                unsigned d = (unsigned)__cvta_generic_to_shared(wsm + ((pb ^ 1) << 12));
                CPA16(d + tid * 16, nsrc + tid * 4);
                CPA_COMMIT();
            }
            const float* wb = wsm + (pb << 12);
            const int k0 = c << 3;
            #pragma unroll
            for (int kk = 0; kk < 8; kk++){
                const float* hr = hsm + (k0 + kk) * 64;
                float h0 = hr[r1], h1 = hr[r2];
                u64 hd0 = pack2(h0, h0), hd1 = pack2(h1, h1);
                #pragma unroll
                for (int q = 0; q < 4; q++){
                    ulonglong2 wq = *reinterpret_cast<const ulonglong2*>(wb + (kk << 9) + (q << 7) + ch0);
                    acc[0][q][0] = fma2(hd0, wq.x, acc[0][q][0]);
                    acc[0][q][1] = fma2(hd0, wq.y, acc[0][q][1]);
                    acc[1][q][0] = fma2(hd1, wq.x, acc[1][q][0]);
                    acc[1][q][1] = fma2(hd1, wq.y, acc[1][q][1]);
                }
            }
            CPA_WAIT();
            __syncthreads();
            pb ^= 1;
        }

        // ================ gates: c in smem, write new h ================
        #pragma unroll
        for (int r = 0; r < 2; r++){
            int rr = r ? r2 : r1;
            #pragma unroll
            for (int p = 0; p < 2; p++){
                float zi0,zi1,zf0,zf1,zg0,zg1,zo0,zo1;
                unpack2(acc[r][0][p], zi0, zi1);
                unpack2(acc[r][1][p], zf0, zf1);
                unpack2(acc[r][2][p], zg0, zg1);
                unpack2(acc[r][3][p], zo0, zo1);
                int hc = ch0 + (p << 1);
                float c0 = csm[hc * 64 + rr], c1 = csm[(hc + 1) * 64 + rr];
                c0 = sig_(zf0)*c0 + sig_(zi0)*tanh_(zg0);
                c1 = sig_(zf1)*c1 + sig_(zi1)*tanh_(zg1);
                csm[ hc      * 64 + rr] = c0;
                csm[(hc + 1) * 64 + rr] = c1;
                hsm[ hc      * 64 + rr] = sig_(zo0)*tanh_(c0);
                hsm[(hc + 1) * 64 + rr] = sig_(zo1)*tanh_(c1);
            }
        }
        __syncthreads();

        // ================ m1 = relu(h @ W1 + b1): 16 active warps x 8 ch ================
        const bool act = (w < 16);
        const int mc0 = w << 3;
        u64 a1[2][4];
        if (act){
            ulonglong2 ba = *reinterpret_cast<const ulonglong2*>(cb1 + mc0);
            ulonglong2 bb = *reinterpret_cast<const ulonglong2*>(cb1 + mc0 + 4);
            a1[0][0]=ba.x; a1[0][1]=ba.y; a1[0][2]=bb.x; a1[0][3]=bb.y;
            a1[1][0]=ba.x; a1[1][1]=ba.y; a1[1][2]=bb.x; a1[1][3]=bb.y;
        }
        for (int c = 0; c < 4; ++c){
            const float* nsrc = (c < 3) ? (W1 + (c + 1) * 4096) : W2;
            {
                unsigned d = (unsigned)__cvta_generic_to_shared(wsm + ((pb ^ 1) << 12));
                CPA16(d + tid * 16, nsrc + tid * 4);
                CPA_COMMIT();
            }
            if (act){
                const float* wb = wsm + (pb << 12);
                const int k0 = c << 5;
                #pragma unroll 8
                for (int kk = 0; kk < 32; kk++){
                    const float* hr = hsm + (k0 + kk) * 64;
                    float h0 = hr[r1], h1 = hr[r2];
                    u64 hd0 = pack2(h0, h0), hd1 = pack2(h1, h1);
                    const float* wr = wb + (kk << 7) + mc0;
                    ulonglong2 wa = *reinterpret_cast<const ulonglong2*>(wr);
                    ulonglong2 wv = *reinterpret_cast<const ulonglong2*>(wr + 4);
                    a1[0][0] = fma2(hd0, wa.x, a1[0][0]);
                    a1[0][1] = fma2(hd0, wa.y, a1[0][1]);
                    a1[0][2] = fma2(hd0, wv.x, a1[0][2]);
                    a1[0][3] = fma2(hd0, wv.y, a1[0][3]);
                    a1[1][0] = fma2(hd1, wa.x, a1[1][0]);
                    a1[1][1] = fma2(hd1, wa.y, a1[1][1]);
                    a1[1][2] = fma2(hd1, wv.x, a1[1][2]);
                    a1[1][3] = fma2(hd1, wv.y, a1[1][3]);
                }
            }
            CPA_WAIT();
            __syncthreads();
            pb ^= 1;
        }
        if (act){
            #pragma unroll
            for (int r = 0; r < 2; r++){
                int rr = r ? r2 : r1;
                #pragma unroll
                for (int j = 0; j < 4; j++){
                    float v0, v1; unpack2(a1[r][j], v0, v1);
                    m1sm[(mc0 + (j<<1)    ) * 64 + rr] = fmaxf(v0, 0.f);
                    m1sm[(mc0 + (j<<1) + 1) * 64 + rr] = fmaxf(v1, 0.f);
                }
            }
        }
        __syncthreads();

        // ================ m2 = relu(m1 @ W2 + b2) + fused out-proj ================
        u64 a2[2][4];
        if (act){
            ulonglong2 ba = *reinterpret_cast<const ulonglong2*>(cb2 + mc0);
            ulonglong2 bb = *reinterpret_cast<const ulonglong2*>(cb2 + mc0 + 4);
            a2[0][0]=ba.x; a2[0][1]=ba.y; a2[0][2]=bb.x; a2[0][3]=bb.y;
            a2[1][0]=ba.x; a2[1][1]=ba.y; a2[1][2]=bb.x; a2[1][3]=bb.y;
        }
        for (int c = 0; c < 4; ++c){
            const float* nsrc = (c < 3) ? (W2 + (c + 1) * 4096) : Wh;  // last: next step z chunk0
            {
                unsigned d = (unsigned)__cvta_generic_to_shared(wsm + ((pb ^ 1) << 12));
                CPA16(d + tid * 16, nsrc + tid * 4);
                CPA_COMMIT();
            }
            if (act){
                const float* wb = wsm + (pb << 12);
                const int k0 = c << 5;
                #pragma unroll 8
                for (int kk = 0; kk < 32; kk++){
                    const float* hr = m1sm + (k0 + kk) * 64;
                    float h0 = hr[r1], h1 = hr[r2];
                    u64 hd0 = pack2(h0, h0), hd1 = pack2(h1, h1);
                    const float* wr = wb + (kk << 7) + mc0;
                    ulonglong2 wa = *reinterpret_cast<const ulonglong2*>(wr);
                    ulonglong2 wv = *reinterpret_cast<const ulonglong2*>(wr + 4);
                    a2[0][0] = fma2(hd0, wa.x, a2[0][0]);
                    a2[0][1] = fma2(hd0, wa.y, a2[0][1]);
                    a2[0][2] = fma2(hd0, wv.x, a2[0][2]);
                    a2[0][3] = fma2(hd0, wv.y, a2[0][3]);
                    a2[1][0] = fma2(hd1, wa.x, a2[1][0]);
                    a2[1][1] = fma2(hd1, wa.y, a2[1][1]);
                    a2[1][2] = fma2(hd1, wv.x, a2[1][2]);
                    a2[1][3] = fma2(hd1, wv.y, a2[1][3]);
                }
            }
            CPA_WAIT();
            __syncthreads();
            pb ^= 1;
        }
        if (act){
            float pr0 = 0.f, pr1 = 0.f;
            #pragma unroll
            for (int j = 0; j < 4; j++){
                float wA = cwo[mc0 + (j<<1)], wB = cwo[mc0 + (j<<1) + 1];
                float v0, v1; unpack2(a2[0][j], v0, v1);
                pr0 += fmaxf(v0, 0.f) * wA + fmaxf(v1, 0.f) * wB;
                unpack2(a2[1][j], v0, v1);
                pr1 += fmaxf(v0, 0.f) * wA + fmaxf(v1, 0.f) * wB;
            }
            red[r1 * 17 + w] = pr0;
            red[r2 * 17 + w] = pr1;
        }
        __syncthreads();
        if (tid < BT){
            float s = boutv;
            #pragma unroll
            for (int j = 0; j < 16; j++) s += red[tid * 17 + j];
            predb[tid] = s;
            out[(b0 + tid) * T_STEPS + t] = s;
        }
        __syncthreads();
    }
}

extern "C" void kernel_launch(void* const* d_in, const int* in_sizes, int n_in,
                              void* d_out, int out_size)
{
    (void)in_sizes; (void)n_in; (void)out_size;
    cudaFuncSetAttribute(fused_lstm_kernel, cudaFuncAttributeMaxDynamicSharedMemorySize, SMEM_BYTES);
    fused_lstm_kernel<<<B_TOT / BT, NT, SMEM_BYTES>>>(
        (const float*)d_in[8],  (const float*)d_in[9],  (const float*)d_in[10],
        (const float*)d_in[11], (const float*)d_in[12], (const float*)d_in[13],
        (const float*)d_in[14], (const float*)d_in[15],
        (const float*)d_in[16], (const float*)d_in[17], (const float*)d_in[18],
        (const float*)d_in[19], (const float*)d_in[20], (const float*)d_in[21],
        (const float*)d_in[22], (const float*)d_in[23], (const float*)d_in[24],
        (float*)d_out);
}

// round 9
// speedup vs baseline: 2.1991x; 2.1991x over previous
#include <cuda_runtime.h>

typedef unsigned long long u64;

#define NT 448
#define BT 56
#define RSTR 58
#define B_TOT 8192
#define T_STEPS 30
#define WARM 24
#define WCH 8192   /* floats per staging chunk (32KB) */

__device__ __forceinline__ u64 pack2(float lo, float hi){
    u64 r; asm("mov.b64 %0, {%1, %2};" : "=l"(r) : "f"(lo), "f"(hi)); return r;
}
__device__ __forceinline__ void unpack2(u64 v, float& lo, float& hi){
    asm("mov.b64 {%0, %1}, %2;" : "=f"(lo), "=f"(hi) : "l"(v));
}
__device__ __forceinline__ u64 fma2(u64 a, u64 b, u64 c){
    u64 d; asm("fma.rn.f32x2 %0, %1, %2, %3;" : "=l"(d) : "l"(a), "l"(b), "l"(c)); return d;
}
__device__ __forceinline__ float sig_(float x){ return __fdividef(1.f, 1.f + __expf(-x)); }
__device__ __forceinline__ float tanh_(float x){ return 1.f - 2.f * __fdividef(1.f, __expf(2.f * x) + 1.f); }

#define CPA16(dst_u32, src) asm volatile("cp.async.cg.shared.global [%0], [%1], 16;" :: "r"(dst_u32), "l"(src))
#define CPA_COMMIT() asm volatile("cp.async.commit_group;")
#define CPA_WAIT()   asm volatile("cp.async.wait_group 0;")

// stage nfloats (multiple of 4) global->smem, no registers held
__device__ __forceinline__ void stage(float* dst, const float* __restrict__ src, int nfloats, int tid){
    unsigned d = (unsigned)__cvta_generic_to_shared(dst);
    for (int i = tid; i < (nfloats >> 2); i += NT)
        CPA16(d + i * 16, src + i * 4);
    CPA_COMMIT();
}

// smem floats: wsm 2*8192 | hbuf 136*58 | m1buf 128*58 | red 112 | predb 56
#define SMEM_FLOATS (2*WCH + 136*RSTR + 128*RSTR + 2*BT + BT)
#define SMEM_BYTES (SMEM_FLOATS * 4)

__global__ void __launch_bounds__(NT, 1)
fused_lstm_kernel(const float* __restrict__ x0, const float* __restrict__ x1,
                  const float* __restrict__ x2, const float* __restrict__ x3,
                  const float* __restrict__ x4, const float* __restrict__ x5,
                  const float* __restrict__ x6, const float* __restrict__ irr,
                  const float* __restrict__ Wi, const float* __restrict__ Wh,
                  const float* __restrict__ bz, const float* __restrict__ W1,
                  const float* __restrict__ b1, const float* __restrict__ W2,
                  const float* __restrict__ b2, const float* __restrict__ Wout,
                  const float* __restrict__ bout, float* __restrict__ out)
{
    extern __shared__ float smem[];
    float* wsm   = smem;                  // 2 x 8192 weight staging (16B aligned)
    float* hbuf  = wsm   + 2 * WCH;       // [136][58]: rows 0-127 h, 128-135 inputs
    float* m1buf = hbuf  + 136 * RSTR;    // [128][58]
    float* red   = m1buf + 128 * RSTR;    // [2][56]
    float* predb = red   + 2 * BT;        // [56]

    const int tid = threadIdx.x;
    const int rg  = tid >> 6;             // 0..6, 8 batch rows each
    const int cg  = tid & 63;             // 0..63, 2 channels each
    const int r0  = rg << 3;
    const int ch0 = cg << 1;
    const int b0  = blockIdx.x * BT;

    // ---- constants to registers ----
    u64 bzr[4];
    #pragma unroll
    for (int q = 0; q < 4; q++) bzr[q] = *reinterpret_cast<const u64*>(&bz[(q << 7) + ch0]);
    const u64 cb1r = *reinterpret_cast<const u64*>(&b1[ch0]);
    const u64 cb2r = *reinterpret_cast<const u64*>(&b2[ch0]);
    const float wo0 = Wout[ch0], wo1 = Wout[ch0 + 1];
    const float boutv = bout[0];

    // ---- input feature pointers: 8 feats x 56 rows ----
    const int lf = tid / BT, lr = tid - lf * BT;
    int lb = b0 + lr; if (lb > B_TOT - 1) lb = B_TOT - 1;
    const float* fptr;
    if      (lf == 0) fptr = x0; else if (lf == 1) fptr = x1;
    else if (lf == 2) fptr = x2; else if (lf == 3) fptr = x3;
    else if (lf == 4) fptr = x4; else if (lf == 5) fptr = x5;
    else if (lf == 6) fptr = x6; else              fptr = irr;
    fptr = (lf < 7) ? (fptr + lb * T_STEPS) : (fptr + lb * WARM);
    const int tmax = (lf < 7) ? (T_STEPS - 1) : (WARM - 1);
    float vin = __ldg(fptr);

    // ---- init h = 0 ----
    for (int i = tid; i < 128 * RSTR; i += NT) hbuf[i] = 0.f;

    // ---- prologue: stage Wh rows 0-15 into wsm[0] ----
    stage(wsm, Wh, WCH, tid);
    CPA_WAIT();
    int pb = 0;

    u64 cst[4][2];
    #pragma unroll
    for (int rp = 0; rp < 4; rp++){ cst[rp][0] = 0ull; cst[rp][1] = 0ull; }

    __syncthreads();

    for (int t = 0; t < T_STEPS; ++t){
        // ---- stage this step's input; prefetch next ----
        {
            float v = (lf < 7 || t < WARM) ? vin : predb[lr];
            hbuf[(128 + lf) * RSTR + lr] = v;
            int tn = (t + 1 < tmax) ? (t + 1) : tmax;
            vin = __ldg(fptr + tn);
        }

        // ================= z = [h, inp] @ [Wh; Wi] + b =================
        u64 acc[4][8];
        #pragma unroll
        for (int q = 0; q < 4; q++){
            float bq0, bq1; unpack2(bzr[q], bq0, bq1);
            u64 p0 = pack2(bq0, bq0), p1 = pack2(bq1, bq1);
            #pragma unroll
            for (int rp = 0; rp < 4; rp++){ acc[rp][(q<<1)] = p0; acc[rp][(q<<1)+1] = p1; }
        }

        // 9 chunks: c0..7 = Wh rows 16c..16c+15, c8 = Wi (8 rows)
        for (int c = 0; c <= 8; ++c){
            // stage next: Wh c+1 | Wi | W1 half 0
            if (c < 7)       stage(wsm + ((pb ^ 1) << 13), Wh + (c + 1) * WCH, WCH, tid);
            else if (c == 7) stage(wsm + ((pb ^ 1) << 13), Wi, 4096, tid);
            else             stage(wsm + ((pb ^ 1) << 13), W1, WCH, tid);

            const float* wb = wsm + (pb << 13);
            const int nk = (c < 8) ? 16 : 8;
            const int k0 = c << 4;
            #pragma unroll 8
            for (int kk = 0; kk < nk; kk++){
                const u64* h64 = reinterpret_cast<const u64*>(hbuf + (k0 + kk) * RSTR + r0);
                u64 hp0 = h64[0], hp1 = h64[1], hp2 = h64[2], hp3 = h64[3];  // 8B-aligned LDS.64
                #pragma unroll
                for (int q = 0; q < 4; q++){
                    u64 wp = *reinterpret_cast<const u64*>(&wb[(kk << 9) + (q << 7) + ch0]);
                    float w0, w1; unpack2(wp, w0, w1);
                    u64 w00 = pack2(w0, w0), w11 = pack2(w1, w1);
                    acc[0][(q<<1)]   = fma2(hp0, w00, acc[0][(q<<1)]);
                    acc[1][(q<<1)]   = fma2(hp1, w00, acc[1][(q<<1)]);
                    acc[2][(q<<1)]   = fma2(hp2, w00, acc[2][(q<<1)]);
                    acc[3][(q<<1)]   = fma2(hp3, w00, acc[3][(q<<1)]);
                    acc[0][(q<<1)+1] = fma2(hp0, w11, acc[0][(q<<1)+1]);
                    acc[1][(q<<1)+1] = fma2(hp1, w11, acc[1][(q<<1)+1]);
                    acc[2][(q<<1)+1] = fma2(hp2, w11, acc[2][(q<<1)+1]);
                    acc[3][(q<<1)+1] = fma2(hp3, w11, acc[3][(q<<1)+1]);
                }
            }
            CPA_WAIT();
            __syncthreads();
            pb ^= 1;
        }

        // ================= gates; c-state in regs; write new h =================
        #pragma unroll
        for (int rp = 0; rp < 4; rp++)
            #pragma unroll
            for (int d = 0; d < 2; d++){
                float zi0,zi1,zf0,zf1,zg0,zg1,zo0,zo1,c0,c1;
                unpack2(acc[rp][0+d], zi0, zi1);
                unpack2(acc[rp][2+d], zf0, zf1);
                unpack2(acc[rp][4+d], zg0, zg1);
                unpack2(acc[rp][6+d], zo0, zo1);
                unpack2(cst[rp][d], c0, c1);
                c0 = sig_(zf0)*c0 + sig_(zi0)*tanh_(zg0);
                c1 = sig_(zf1)*c1 + sig_(zi1)*tanh_(zg1);
                cst[rp][d] = pack2(c0, c1);
                float h0 = sig_(zo0)*tanh_(c0);
                float h1 = sig_(zo1)*tanh_(c1);
                *reinterpret_cast<u64*>(&hbuf[(ch0+d)*RSTR + r0 + (rp<<1)]) = pack2(h0, h1);
            }
        __syncthreads();

        // ================= m1 = relu(h @ W1 + b1): 2 chunks x 64 rows =================
        u64 a1[4][2];
        {
            float q0, q1; unpack2(cb1r, q0, q1);
            u64 p0 = pack2(q0,q0), p1 = pack2(q1,q1);
            #pragma unroll
            for (int rp = 0; rp < 4; rp++){ a1[rp][0] = p0; a1[rp][1] = p1; }
        }
        for (int c = 0; c < 2; ++c){
            if (c == 0) stage(wsm + ((pb ^ 1) << 13), W1 + WCH, WCH, tid);
            else        stage(wsm + ((pb ^ 1) << 13), W2, WCH, tid);

            const float* wb = wsm + (pb << 13);
            const int k0 = c << 6;
            #pragma unroll 8
            for (int kk = 0; kk < 64; kk++){
                const u64* h64 = reinterpret_cast<const u64*>(hbuf + (k0 + kk) * RSTR + r0);
                u64 hp0 = h64[0], hp1 = h64[1], hp2 = h64[2], hp3 = h64[3];
                u64 wp = *reinterpret_cast<const u64*>(&wb[(kk << 7) + ch0]);
                float w0, w1; unpack2(wp, w0, w1);
                u64 w00 = pack2(w0, w0), w11 = pack2(w1, w1);
                a1[0][0] = fma2(hp0, w00, a1[0][0]);
                a1[1][0] = fma2(hp1, w00, a1[1][0]);
                a1[2][0] = fma2(hp2, w00, a1[2][0]);
                a1[3][0] = fma2(hp3, w00, a1[3][0]);
                a1[0][1] = fma2(hp0, w11, a1[0][1]);
                a1[1][1] = fma2(hp1, w11, a1[1][1]);
                a1[2][1] = fma2(hp2, w11, a1[2][1]);
                a1[3][1] = fma2(hp3, w11, a1[3][1]);
            }
            CPA_WAIT();
            __syncthreads();
            pb ^= 1;
        }
        #pragma unroll
        for (int rp = 0; rp < 4; rp++)
            #pragma unroll
            for (int d = 0; d < 2; d++){
                float v0, v1; unpack2(a1[rp][d], v0, v1);
                *reinterpret_cast<u64*>(&m1buf[(ch0+d)*RSTR + r0 + (rp<<1)]) =
                    pack2(fmaxf(v0, 0.f), fmaxf(v1, 0.f));
            }
        __syncthreads();

        // ================= m2 = relu(m1 @ W2 + b2): 2 chunks =================
        u64 a2[4][2];
        {
            float q0, q1; unpack2(cb2r, q0, q1);
            u64 p0 = pack2(q0,q0), p1 = pack2(q1,q1);
            #pragma unroll
            for (int rp = 0; rp < 4; rp++){ a2[rp][0] = p0; a2[rp][1] = p1; }
        }
        for (int c = 0; c < 2; ++c){
            if (c == 0) stage(wsm + ((pb ^ 1) << 13), W2 + WCH, WCH, tid);
            else        stage(wsm + ((pb ^ 1) << 13), Wh, WCH, tid);  // next step chunk 0

            const float* wb = wsm + (pb << 13);
            const int k0 = c << 6;
            #pragma unroll 8
            for (int kk = 0; kk < 64; kk++){
                const u64* h64 = reinterpret_cast<const u64*>(m1buf + (k0 + kk) * RSTR + r0);
                u64 hp0 = h64[0], hp1 = h64[1], hp2 = h64[2], hp3 = h64[3];
                u64 wp = *reinterpret_cast<const u64*>(&wb[(kk << 7) + ch0]);
                float w0, w1; unpack2(wp, w0, w1);
                u64 w00 = pack2(w0, w0), w11 = pack2(w1, w1);
                a2[0][0] = fma2(hp0, w00, a2[0][0]);
                a2[1][0] = fma2(hp1, w00, a2[1][0]);
                a2[2][0] = fma2(hp2, w00, a2[2][0]);
                a2[3][0] = fma2(hp3, w00, a2[3][0]);
                a2[0][1] = fma2(hp0, w11, a2[0][1]);
                a2[1][1] = fma2(hp1, w11, a2[1][1]);
                a2[2][1] = fma2(hp2, w11, a2[2][1]);
                a2[3][1] = fma2(hp3, w11, a2[3][1]);
            }
            CPA_WAIT();
            __syncthreads();
            pb ^= 1;
        }

        // ---- out-projection in registers + warp shuffle reduce ----
        float p[8];
        #pragma unroll
        for (int rp = 0; rp < 4; rp++){
            float v0a, v0b, v1a, v1b;
            unpack2(a2[rp][0], v0a, v0b);
            unpack2(a2[rp][1], v1a, v1b);
            p[(rp<<1)  ] = fmaxf(v0a, 0.f) * wo0 + fmaxf(v1a, 0.f) * wo1;
            p[(rp<<1)+1] = fmaxf(v0b, 0.f) * wo0 + fmaxf(v1b, 0.f) * wo1;
        }
        #pragma unroll
        for (int j = 0; j < 8; j++)
            #pragma unroll
            for (int off = 16; off; off >>= 1)
                p[j] += __shfl_xor_sync(0xffffffffu, p[j], off);
        if ((tid & 31) == 0){
            int half = (tid >> 5) & 1;
            #pragma unroll
            for (int j = 0; j < 8; j++) red[half * BT + r0 + j] = p[j];
        }
        __syncthreads();
        if (tid < BT){
            float s = boutv + red[tid] + red[BT + tid];
            predb[tid] = s;
            int bb = b0 + tid;
            if (bb < B_TOT) out[bb * T_STEPS + t] = s;
        }
        __syncthreads();
    }
}

extern "C" void kernel_launch(void* const* d_in, const int* in_sizes, int n_in,
                              void* d_out, int out_size)
{
    (void)in_sizes; (void)n_in; (void)out_size;
    cudaFuncSetAttribute(fused_lstm_kernel, cudaFuncAttributeMaxDynamicSharedMemorySize, SMEM_BYTES);
    int grid = (B_TOT + BT - 1) / BT; // 147
    fused_lstm_kernel<<<grid, NT, SMEM_BYTES>>>(
        (const float*)d_in[8],  (const float*)d_in[9],  (const float*)d_in[10],
        (const float*)d_in[11], (const float*)d_in[12], (const float*)d_in[13],
        (const float*)d_in[14], (const float*)d_in[15],
        (const float*)d_in[16], (const float*)d_in[17], (const float*)d_in[18],
        (const float*)d_in[19], (const float*)d_in[20], (const float*)d_in[21],
        (const float*)d_in[22], (const float*)d_in[23], (const float*)d_in[24],
        (float*)d_out);
}

// round 10
// speedup vs baseline: 2.2845x; 1.0389x over previous
#include <cuda_runtime.h>

typedef unsigned long long u64;

#define NT 640
#define BT 60
#define RSTR 62
#define B_TOT 8192
#define T_STEPS 30
#define WARM 24
#define WCH 8192   /* floats per staging chunk (32KB) */

__device__ __forceinline__ u64 pack2(float lo, float hi){
    u64 r; asm("mov.b64 %0, {%1, %2};" : "=l"(r) : "f"(lo), "f"(hi)); return r;
}
__device__ __forceinline__ void unpack2(u64 v, float& lo, float& hi){
    asm("mov.b64 {%0, %1}, %2;" : "=f"(lo), "=f"(hi) : "l"(v));
}
__device__ __forceinline__ u64 fma2(u64 a, u64 b, u64 c){
    u64 d; asm("fma.rn.f32x2 %0, %1, %2, %3;" : "=l"(d) : "l"(a), "l"(b), "l"(c)); return d;
}
__device__ __forceinline__ float sig_(float x){ return __fdividef(1.f, 1.f + __expf(-x)); }
__device__ __forceinline__ float tanh_(float x){ return 1.f - 2.f * __fdividef(1.f, __expf(2.f * x) + 1.f); }

#define CPA16(dst_u32, src) asm volatile("cp.async.cg.shared.global [%0], [%1], 16;" :: "r"(dst_u32), "l"(src))
#define CPA_COMMIT() asm volatile("cp.async.commit_group;")
#define CPA_WAIT()   asm volatile("cp.async.wait_group 0;")

__device__ __forceinline__ void stage(float* dst, const float* __restrict__ src, int nfloats, int tid){
    unsigned d = (unsigned)__cvta_generic_to_shared(dst);
    for (int i = tid; i < (nfloats >> 2); i += NT)
        CPA16(d + i * 16, src + i * 4);
    CPA_COMMIT();
}

// smem floats: wsm 2*8192 | hbuf 136*62 | m1buf 128*62 | cbz 512 | cb1,cb2,cwo 384 | red 120 | predb 60
#define SMEM_FLOATS (2*WCH + 136*RSTR + 128*RSTR + 512 + 384 + 2*BT + BT)
#define SMEM_BYTES (SMEM_FLOATS * 4)

__global__ void __launch_bounds__(NT, 1)
fused_lstm_kernel(const float* __restrict__ x0, const float* __restrict__ x1,
                  const float* __restrict__ x2, const float* __restrict__ x3,
                  const float* __restrict__ x4, const float* __restrict__ x5,
                  const float* __restrict__ x6, const float* __restrict__ irr,
                  const float* __restrict__ Wi, const float* __restrict__ Wh,
                  const float* __restrict__ bz, const float* __restrict__ W1,
                  const float* __restrict__ b1, const float* __restrict__ W2,
                  const float* __restrict__ b2, const float* __restrict__ Wout,
                  const float* __restrict__ bout, float* __restrict__ out)
{
    extern __shared__ float smem[];
    float* wsm   = smem;                  // 2 x 8192 weight staging
    float* hbuf  = wsm   + 2 * WCH;       // [136][62]: rows 0-127 h, 128-135 inputs
    float* m1buf = hbuf  + 136 * RSTR;    // [128][62]
    float* cbz   = m1buf + 128 * RSTR;    // 512
    float* cb1   = cbz   + 512;           // 128
    float* cb2   = cb1   + 128;           // 128
    float* cwo   = cb2   + 128;           // 128
    float* red   = cwo   + 128;           // [2][60]
    float* predb = red   + 2 * BT;        // [60]

    const int tid = threadIdx.x;
    const int rg  = tid >> 6;             // 0..9, 6 batch rows each
    const int cg  = tid & 63;             // 0..63, 2 channels each
    const int r0  = rg * 6;
    const int ch0 = cg << 1;
    const int b0  = blockIdx.x * BT;

    for (int i = tid; i < 512; i += NT) cbz[i] = bz[i];
    if (tid < 128){ cb1[tid] = b1[tid]; cb2[tid] = b2[tid]; cwo[tid] = Wout[tid]; }
    const float boutv = bout[0];

    const int lf = tid / BT, lr = tid - lf * BT;
    const float* fptr = x0; int tmax = 0;
    if (tid < 8 * BT){
        int lb = b0 + lr; if (lb > B_TOT - 1) lb = B_TOT - 1;
        const float* p;
        if      (lf == 0) p = x0; else if (lf == 1) p = x1;
        else if (lf == 2) p = x2; else if (lf == 3) p = x3;
        else if (lf == 4) p = x4; else if (lf == 5) p = x5;
        else if (lf == 6) p = x6; else              p = irr;
        fptr = (lf < 7) ? (p + lb * T_STEPS) : (p + lb * WARM);
        tmax = (lf < 7) ? (T_STEPS - 1) : (WARM - 1);
    }

    for (int i = tid; i < 128 * RSTR; i += NT) hbuf[i] = 0.f;

    stage(wsm, Wh, WCH, tid);
    CPA_WAIT();
    int pb = 0;

    u64 cst[3][2];
    #pragma unroll
    for (int rp = 0; rp < 3; rp++){ cst[rp][0] = 0ull; cst[rp][1] = 0ull; }

    __syncthreads();

    for (int t = 0; t < T_STEPS; ++t){
        if (tid < 8 * BT){
            int ti = t < tmax ? t : tmax;
            float gv = __ldg(fptr + ti);
            float v = (lf < 7 || t < WARM) ? gv : predb[lr];
            hbuf[(128 + lf) * RSTR + lr] = v;
        }

        // ================= z = [h, inp] @ [Wh; Wi] + b =================
        u64 acc[3][8];
        #pragma unroll
        for (int q = 0; q < 4; q++)
            #pragma unroll
            for (int d = 0; d < 2; d++){
                float bv = cbz[(q << 7) + ch0 + d];
                u64 p = pack2(bv, bv);
                acc[0][(q<<1)+d] = p; acc[1][(q<<1)+d] = p; acc[2][(q<<1)+d] = p;
            }

        for (int c = 0; c <= 8; ++c){
            if (c < 7)       stage(wsm + ((pb ^ 1) << 13), Wh + (c + 1) * WCH, WCH, tid);
            else if (c == 7) stage(wsm + ((pb ^ 1) << 13), Wi, 4096, tid);
            else             stage(wsm + ((pb ^ 1) << 13), W1, WCH, tid);

            const float* wb = wsm + (pb << 13);
            const int nk = (c < 8) ? 16 : 8;
            const int k0 = c << 4;
            #pragma unroll 8
            for (int kk = 0; kk < nk; kk++){
                const u64* h64 = reinterpret_cast<const u64*>(hbuf + (k0 + kk) * RSTR + r0);
                u64 hp0 = h64[0], hp1 = h64[1], hp2 = h64[2];
                #pragma unroll
                for (int q = 0; q < 4; q++){
                    u64 wp = *reinterpret_cast<const u64*>(&wb[(kk << 9) + (q << 7) + ch0]);
                    float w0, w1; unpack2(wp, w0, w1);
                    u64 w00 = pack2(w0, w0), w11 = pack2(w1, w1);
                    acc[0][(q<<1)]   = fma2(hp0, w00, acc[0][(q<<1)]);
                    acc[1][(q<<1)]   = fma2(hp1, w00, acc[1][(q<<1)]);
                    acc[2][(q<<1)]   = fma2(hp2, w00, acc[2][(q<<1)]);
                    acc[0][(q<<1)+1] = fma2(hp0, w11, acc[0][(q<<1)+1]);
                    acc[1][(q<<1)+1] = fma2(hp1, w11, acc[1][(q<<1)+1]);
                    acc[2][(q<<1)+1] = fma2(hp2, w11, acc[2][(q<<1)+1]);
                }
            }
            CPA_WAIT();
            __syncthreads();
            pb ^= 1;
        }

        // ================= gates; c-state in regs; write new h =================
        #pragma unroll
        for (int rp = 0; rp < 3; rp++)
            #pragma unroll
            for (int d = 0; d < 2; d++){
                float zi0,zi1,zf0,zf1,zg0,zg1,zo0,zo1,c0,c1;
                unpack2(acc[rp][0+d], zi0, zi1);
                unpack2(acc[rp][2+d], zf0, zf1);
                unpack2(acc[rp][4+d], zg0, zg1);
                unpack2(acc[rp][6+d], zo0, zo1);
                unpack2(cst[rp][d], c0, c1);
                c0 = sig_(zf0)*c0 + sig_(zi0)*tanh_(zg0);
                c1 = sig_(zf1)*c1 + sig_(zi1)*tanh_(zg1);
                cst[rp][d] = pack2(c0, c1);
                float h0 = sig_(zo0)*tanh_(c0);
                float h1 = sig_(zo1)*tanh_(c1);
                *reinterpret_cast<u64*>(&hbuf[(ch0+d)*RSTR + r0 + (rp<<1)]) = pack2(h0, h1);
            }
        __syncthreads();

        // ================= m1 = relu(h @ W1 + b1) =================
        u64 a1[3][2];
        {
            float q0 = cb1[ch0], q1 = cb1[ch0 + 1];
            u64 p0 = pack2(q0,q0), p1 = pack2(q1,q1);
            a1[0][0]=p0; a1[1][0]=p0; a1[2][0]=p0;
            a1[0][1]=p1; a1[1][1]=p1; a1[2][1]=p1;
        }
        for (int c = 0; c < 2; ++c){
            if (c == 0) stage(wsm + ((pb ^ 1) << 13), W1 + WCH, WCH, tid);
            else        stage(wsm + ((pb ^ 1) << 13), W2, WCH, tid);

            const float* wb = wsm + (pb << 13);
            const int k0 = c << 6;
            #pragma unroll 8
            for (int kk = 0; kk < 64; kk++){
                const u64* h64 = reinterpret_cast<const u64*>(hbuf + (k0 + kk) * RSTR + r0);
                u64 hp0 = h64[0], hp1 = h64[1], hp2 = h64[2];
                u64 wp = *reinterpret_cast<const u64*>(&wb[(kk << 7) + ch0]);
                float w0, w1; unpack2(wp, w0, w1);
                u64 w00 = pack2(w0, w0), w11 = pack2(w1, w1);
                a1[0][0] = fma2(hp0, w00, a1[0][0]);
                a1[1][0] = fma2(hp1, w00, a1[1][0]);
                a1[2][0] = fma2(hp2, w00, a1[2][0]);
                a1[0][1] = fma2(hp0, w11, a1[0][1]);
                a1[1][1] = fma2(hp1, w11, a1[1][1]);
                a1[2][1] = fma2(hp2, w11, a1[2][1]);
            }
            CPA_WAIT();
            __syncthreads();
            pb ^= 1;
        }
        #pragma unroll
        for (int rp = 0; rp < 3; rp++)
            #pragma unroll
            for (int d = 0; d < 2; d++){
                float v0, v1; unpack2(a1[rp][d], v0, v1);
                *reinterpret_cast<u64*>(&m1buf[(ch0+d)*RSTR + r0 + (rp<<1)]) =
                    pack2(fmaxf(v0, 0.f), fmaxf(v1, 0.f));
            }
        __syncthreads();

        // ================= m2 = relu(m1 @ W2 + b2) =================
        u64 a2[3][2];
        {
            float q0 = cb2[ch0], q1 = cb2[ch0 + 1];
            u64 p0 = pack2(q0,q0), p1 = pack2(q1,q1);
            a2[0][0]=p0; a2[1][0]=p0; a2[2][0]=p0;
            a2[0][1]=p1; a2[1][1]=p1; a2[2][1]=p1;
        }
        for (int c = 0; c < 2; ++c){
            if (c == 0) stage(wsm + ((pb ^ 1) << 13), W2 + WCH, WCH, tid);
            else        stage(wsm + ((pb ^ 1) << 13), Wh, WCH, tid);

            const float* wb = wsm + (pb << 13);
            const int k0 = c << 6;
            #pragma unroll 8
            for (int kk = 0; kk < 64; kk++){
                const u64* h64 = reinterpret_cast<const u64*>(m1buf + (k0 + kk) * RSTR + r0);
                u64 hp0 = h64[0], hp1 = h64[1], hp2 = h64[2];
                u64 wp = *reinterpret_cast<const u64*>(&wb[(kk << 7) + ch0]);
                float w0, w1; unpack2(wp, w0, w1);
                u64 w00 = pack2(w0, w0), w11 = pack2(w1, w1);
                a2[0][0] = fma2(hp0, w00, a2[0][0]);
                a2[1][0] = fma2(hp1, w00, a2[1][0]);
                a2[2][0] = fma2(hp2, w00, a2[2][0]);
                a2[0][1] = fma2(hp0, w11, a2[0][1]);
                a2[1][1] = fma2(hp1, w11, a2[1][1]);
                a2[2][1] = fma2(hp2, w11, a2[2][1]);
            }
            CPA_WAIT();
            __syncthreads();
            pb ^= 1;
        }

        // ---- out-projection + warp shuffle reduce ----
        float p[6];
        {
            float wo0 = cwo[ch0], wo1 = cwo[ch0 + 1];
            #pragma unroll
            for (int rp = 0; rp < 3; rp++){
                float v0a, v0b, v1a, v1b;
                unpack2(a2[rp][0], v0a, v0b);
                unpack2(a2[rp][1], v1a, v1b);
                p[(rp<<1)  ] = fmaxf(v0a, 0.f) * wo0 + fmaxf(v1a, 0.f) * wo1;
                p[(rp<<1)+1] = fmaxf(v0b, 0.f) * wo0 + fmaxf(v1b, 0.f) * wo1;
            }
        }
        #pragma unroll
        for (int j = 0; j < 6; j++)
            #pragma unroll
            for (int off = 16; off; off >>= 1)
                p[j] += __shfl_xor_sync(0xffffffffu, p[j], off);
        if ((tid & 31) == 0){
            int half = (tid >> 5) & 1;
            #pragma unroll
            for (int j = 0; j < 6; j++) red[half * BT + r0 + j] = p[j];
        }
        __syncthreads();
        if (tid < BT){
            float s = boutv + red[tid] + red[BT + tid];
            predb[tid] = s;
            int bb = b0 + tid;
            if (bb < B_TOT) out[bb * T_STEPS + t] = s;
        }
        __syncthreads();
    }
}

extern "C" void kernel_launch(void* const* d_in, const int* in_sizes, int n_in,
                              void* d_out, int out_size)
{
    (void)in_sizes; (void)n_in; (void)out_size;
    cudaFuncSetAttribute(fused_lstm_kernel, cudaFuncAttributeMaxDynamicSharedMemorySize, SMEM_BYTES);
    int grid = (B_TOT + BT - 1) / BT; // 137
    fused_lstm_kernel<<<grid, NT, SMEM_BYTES>>>(
        (const float*)d_in[8],  (const float*)d_in[9],  (const float*)d_in[10],
        (const float*)d_in[11], (const float*)d_in[12], (const float*)d_in[13],
        (const float*)d_in[14], (const float*)d_in[15],
        (const float*)d_in[16], (const float*)d_in[17], (const float*)d_in[18],
        (const float*)d_in[19], (const float*)d_in[20], (const float*)d_in[21],
        (const float*)d_in[22], (const float*)d_in[23], (const float*)d_in[24],
        (float*)d_out);
}